// round 12
// baseline (speedup 1.0000x reference)
#include <cuda_runtime.h>
#include <cuda_bf16.h>
#include <cstdint>

#define XDIM 128
#define X3   (XDIM * XDIM * XDIM)   // 2,097,152 voxels
#define NB   16                     // batch
#define ZBLOCKS 489                 // zero work blocks: 489*256*4 >= 500000
#define ZT   (ZBLOCKS * 256)

// Grid in bf16, batch-minor: g_grid[v*NB + b]. 64 MiB, zero-init at load.
// INVARIANT: all-zero at entry to every kernel_launch. Per launch:
// scatter -> reduce -> zero(touched)+finalize (restores invariant).
// PDL overlaps each kernel's prologue with its predecessor's tail.
__device__ __nv_bfloat16 g_grid[(size_t)X3 * NB];
__device__ double g_acc[2 * NB];   // [0..15] tv sums, [16..31] mse sums

__device__ __forceinline__ void pdl_wait()    {
    asm volatile("griddepcontrol.wait;" ::: "memory");
}
__device__ __forceinline__ void pdl_trigger() {
    asm volatile("griddepcontrol.launch_dependents;" ::: "memory");
}

// ---------------------------------------------------------------------------
// Scatter (r5 proven): one thread per index; 2 x red.v4.bf16x2 (16 batches).
// Triggers dependents right after issuing its reductions.
// ---------------------------------------------------------------------------
__global__ void scatter_kernel(const int* __restrict__ idx,
                               const float* __restrict__ vals, int N) {
    int n = blockIdx.x * blockDim.x + threadIdx.x;
    if (n < N) {
        int z = __ldcs(idx + 3 * n + 0);
        int y = __ldcs(idx + 3 * n + 1);
        int x = __ldcs(idx + 3 * n + 2);
        size_t v = (size_t)(((z << 7) + y) * XDIM + x);

        unsigned w[8];
#pragma unroll
        for (int g = 0; g < 8; g++) {
            float a = __ldcs(vals + (size_t)(2 * g) * N + n);
            float b = __ldcs(vals + (size_t)(2 * g + 1) * N + n);
            __nv_bfloat162 p = __floats2bfloat162_rn(a, b);
            w[g] = *reinterpret_cast<unsigned*>(&p);
        }

        __nv_bfloat16* base = g_grid + v * NB;
        asm volatile("red.global.add.noftz.v4.bf16x2 [%0], {%1, %2, %3, %4};"
                     :: "l"(base), "r"(w[0]), "r"(w[1]), "r"(w[2]), "r"(w[3])
                     : "memory");
        asm volatile("red.global.add.noftz.v4.bf16x2 [%0], {%1, %2, %3, %4};"
                     :: "l"(base + 8), "r"(w[4]), "r"(w[5]), "r"(w[6]), "r"(w[7])
                     : "memory");
    }
    pdl_trigger();
}

// ---------------------------------------------------------------------------
// Packed diff-accumulate (proven r4): HADD2 diff, shl/and unpack, FADD |.|
// TV, packed fma.rn.f32x2 MSE.
// ---------------------------------------------------------------------------
#define ACCW(sw, nw, k, mp) do {                                              \
    __nv_bfloat162 _a = *reinterpret_cast<const __nv_bfloat162*>(&(nw));      \
    __nv_bfloat162 _b = *reinterpret_cast<const __nv_bfloat162*>(&(sw));      \
    __nv_bfloat162 _d = __hsub2(_a, _b);                                      \
    unsigned _du = *reinterpret_cast<unsigned*>(&_d);                         \
    float _lo = __uint_as_float(_du << 16);                                   \
    float _hi = __uint_as_float(_du & 0xffff0000u);                           \
    tv[(k)]     += fabsf(_lo);                                                \
    tv[(k) + 1] += fabsf(_hi);                                                \
    unsigned long long _dp;                                                   \
    asm("mov.b64 %0, {%1, %2};" : "=l"(_dp)                                   \
        : "r"(__float_as_uint(_lo)), "r"(__float_as_uint(_hi)));              \
    asm("fma.rn.f32x2 %0, %1, %2, %3;" : "=l"(mp)                             \
        : "l"(_dp), "l"(_dp), "l"(mp));                                       \
} while (0)

#define ACC4(s, nb) do {                                                      \
    ACCW((s).x, (nb).x, 0, msep[0]);                                          \
    ACCW((s).y, (nb).y, 2, msep[1]);                                          \
    ACCW((s).z, (nb).z, 4, msep[2]);                                          \
    ACCW((s).w, (nb).w, 6, msep[3]);                                          \
} while (0)

// ---------------------------------------------------------------------------
// Reduce (r5 proven tiling): grid = 16 y-octets x 32 z-quads, block = 8
// warps, warp = one y row, 4 z-plane loop. Setup pre-wait; grid loads after
// pdl_wait; dependents triggered before the reduction epilogue.
// ---------------------------------------------------------------------------
__global__ void reduce_kernel() {
    const uint4* __restrict__ g4 = (const uint4*)g_grid;
    int tid  = threadIdx.x;
    int lane = tid & 31;
    int wrp  = tid >> 5;             // 0..7
    int bg   = lane & 1;
    int xl   = lane >> 1;            // 0..15
    int y    = blockIdx.x * 8 + wrp; // 0..127
    bool yok = (y < XDIM - 1);

    float tv[8];
    unsigned long long msep[4];
#pragma unroll
    for (int i = 0; i < 8; i++) tv[i] = 0.f;
#pragma unroll
    for (int i = 0; i < 4; i++) msep[i] = 0ull;

    pdl_wait();                      // scatter results must be visible

    for (int zi = 0; zi < 4; zi++) {
        int z = blockIdx.y * 4 + zi;
        bool zok = (z < XDIM - 1);
        size_t row2 = ((size_t)(z << 7) + y) * (XDIM * 2);  // uint4 idx at x=0

#pragma unroll
        for (int c = 0; c < 8; c++) {
            size_t i0 = row2 + c * 32 + lane;
            uint4 s = g4[i0];

            if (c < 7) {
                uint4 nx = g4[i0 + 2];
                ACC4(s, nx);
            } else if (xl < 15) {                  // x = 112..126 only
                uint4 nx = g4[i0 + 2];
                ACC4(s, nx);
            }
            if (yok) { uint4 ny = g4[i0 + 2 * XDIM];        ACC4(s, ny); }
            if (zok) { uint4 nz = g4[i0 + 2 * XDIM * XDIM]; ACC4(s, nz); }
        }
    }

    pdl_trigger();                   // grid reads done; let zero_fin launch

    // Unpack packed mse pairs.
    float mse[8];
#pragma unroll
    for (int i = 0; i < 4; i++) {
        unsigned _lo, _hi;
        asm("mov.b64 {%0, %1}, %2;" : "=r"(_lo), "=r"(_hi) : "l"(msep[i]));
        mse[2 * i]     = __uint_as_float(_lo);
        mse[2 * i + 1] = __uint_as_float(_hi);
    }

    // Warp reduce over lanes sharing bg (stride-2 lanes): xor 2,4,8,16.
#pragma unroll
    for (int off = 2; off <= 16; off <<= 1) {
#pragma unroll
        for (int i = 0; i < 8; i++) {
            tv[i]  += __shfl_xor_sync(0xffffffffu, tv[i],  off);
            mse[i] += __shfl_xor_sync(0xffffffffu, mse[i], off);
        }
    }

    __shared__ float s_tv[NB], s_mse[NB];
    if (tid < NB) { s_tv[tid] = 0.f; s_mse[tid] = 0.f; }
    __syncthreads();

    if (lane < 2) {                  // lane 0 = bg0 totals, lane 1 = bg1
#pragma unroll
        for (int i = 0; i < 8; i++) {
            atomicAdd(&s_tv[bg * 8 + i],  tv[i]);
            atomicAdd(&s_mse[bg * 8 + i], mse[i]);
        }
    }
    __syncthreads();

    if (tid < NB) {
        atomicAdd(&g_acc[tid],      (double)s_tv[tid]);
        atomicAdd(&g_acc[NB + tid], (double)s_mse[tid]);
    }
}

// ---------------------------------------------------------------------------
// Zero the touched voxels (4 indices/thread, 490 co-resident blocks). All
// index loads + address math run PRE-wait (overlapping reduce's tail); the
// grid stores and finalize run post-wait.
// ---------------------------------------------------------------------------
__global__ void zero_fin_kernel(const int* __restrict__ idx, int N,
                                float* __restrict__ out) {
    int g = blockIdx.x * blockDim.x + threadIdx.x;
    const int n0 = g, n1 = g + ZT, n2 = g + 2 * ZT, n3 = g + 3 * ZT;
    const bool k0 = n0 < N, k1 = n1 < N, k2 = n2 < N, k3 = n3 < N;
    const bool fin = (blockIdx.x == ZBLOCKS) && (threadIdx.x < 32);

    // --- pre-wait: stream the index reads (overlaps reduce epilogue) ------
    size_t v0 = 0, v1 = 0, v2 = 0, v3 = 0;
    if (k0) { int z = __ldcs(idx + 3 * n0), y = __ldcs(idx + 3 * n0 + 1),
                  x = __ldcs(idx + 3 * n0 + 2);
              v0 = (size_t)(((z << 7) + y) * XDIM + x); }
    if (k1) { int z = __ldcs(idx + 3 * n1), y = __ldcs(idx + 3 * n1 + 1),
                  x = __ldcs(idx + 3 * n1 + 2);
              v1 = (size_t)(((z << 7) + y) * XDIM + x); }
    if (k2) { int z = __ldcs(idx + 3 * n2), y = __ldcs(idx + 3 * n2 + 1),
                  x = __ldcs(idx + 3 * n2 + 2);
              v2 = (size_t)(((z << 7) + y) * XDIM + x); }
    if (k3) { int z = __ldcs(idx + 3 * n3), y = __ldcs(idx + 3 * n3 + 1),
                  x = __ldcs(idx + 3 * n3 + 2);
              v3 = (size_t)(((z << 7) + y) * XDIM + x); }

    pdl_wait();                      // reduce must have read the grid / g_acc

    ulonglong4 z4 = make_ulonglong4(0ull, 0ull, 0ull, 0ull);
    if (k0) *(ulonglong4*)(g_grid + v0 * NB) = z4;
    if (k1) *(ulonglong4*)(g_grid + v1 * NB) = z4;
    if (k2) *(ulonglong4*)(g_grid + v2 * NB) = z4;
    if (k3) *(ulonglong4*)(g_grid + v3 * NB) = z4;

    if (fin) {
        int t = threadIdx.x;
        double norm = (t < NB) ? (double)X3
                               : (double)(2 * XDIM * XDIM - 2 * XDIM);
        out[t] = (float)(g_acc[t] / norm);
        g_acc[t] = 0.0;              // restore invariant for next replay
    }
}

extern "C" void kernel_launch(void* const* d_in, const int* in_sizes, int n_in,
                              void* d_out, int out_size) {
    const int*   indices = (const int*)d_in[0];
    const float* values  = (const float*)d_in[1];
    int N = in_sizes[0] / 3;        // 500000

    scatter_kernel<<<(N + 255) / 256, 256>>>(indices, values, N);

    cudaLaunchAttribute attr;
    attr.id = cudaLaunchAttributeProgrammaticStreamSerialization;
    attr.val.programmaticStreamSerializationAllowed = 1;

    cudaLaunchConfig_t cfg = {};
    cfg.gridDim  = dim3(16, 32);
    cfg.blockDim = dim3(256);
    cfg.dynamicSmemBytes = 0;
    cfg.stream = 0;
    cfg.attrs = &attr;
    cfg.numAttrs = 1;
    cudaLaunchKernelEx(&cfg, reduce_kernel);

    cfg.gridDim = dim3(ZBLOCKS + 1);
    cudaLaunchKernelEx(&cfg, zero_fin_kernel, indices, N, (float*)d_out);
}

// round 13
// speedup vs baseline: 1.5243x; 1.5243x over previous
#include <cuda_runtime.h>
#include <cuda_bf16.h>
#include <cstdint>

#define XDIM 128
#define X3   (XDIM * XDIM * XDIM)   // 2,097,152 voxels
#define NB   16                     // batch

// Grid in bf16, batch-minor: g_grid[v*NB + b]. 64 MiB, zero-init at load.
// INVARIANT: all-zero at entry to every kernel_launch. Per launch:
// scatter -> reduce (self-zeroes nonzero INTERIOR voxels: y%8!=0 && z%4!=0,
// which only their own block reads) -> zero boundary voxels (y%8==0 ||
// z%4==0) + finalize. Nonzero bits <=> touched: bf16 accumulator starting at
// +0 under RN addition can never become -0.0 or a nonzero encoding of zero.
__device__ __nv_bfloat16 g_grid[(size_t)X3 * NB];
__device__ double g_acc[2 * NB];   // [0..15] tv sums, [16..31] mse sums

// ---------------------------------------------------------------------------
// Scatter (r5 proven): one thread per index; 2 x red.v4.bf16x2 (16 batches).
// ---------------------------------------------------------------------------
__global__ void scatter_kernel(const int* __restrict__ idx,
                               const float* __restrict__ vals, int N) {
    int n = blockIdx.x * blockDim.x + threadIdx.x;
    if (n >= N) return;
    int z = __ldcs(idx + 3 * n + 0);
    int y = __ldcs(idx + 3 * n + 1);
    int x = __ldcs(idx + 3 * n + 2);
    size_t v = (size_t)(((z << 7) + y) * XDIM + x);

    unsigned w[8];
#pragma unroll
    for (int g = 0; g < 8; g++) {
        float a = __ldcs(vals + (size_t)(2 * g) * N + n);
        float b = __ldcs(vals + (size_t)(2 * g + 1) * N + n);
        __nv_bfloat162 p = __floats2bfloat162_rn(a, b);
        w[g] = *reinterpret_cast<unsigned*>(&p);
    }

    __nv_bfloat16* base = g_grid + v * NB;
    asm volatile("red.global.add.noftz.v4.bf16x2 [%0], {%1, %2, %3, %4};"
                 :: "l"(base), "r"(w[0]), "r"(w[1]), "r"(w[2]), "r"(w[3])
                 : "memory");
    asm volatile("red.global.add.noftz.v4.bf16x2 [%0], {%1, %2, %3, %4};"
                 :: "l"(base + 8), "r"(w[4]), "r"(w[5]), "r"(w[6]), "r"(w[7])
                 : "memory");
}

// ---------------------------------------------------------------------------
// Packed diff-accumulate (proven r4): HADD2 diff, shl/and unpack, FADD |.|
// TV, packed fma.rn.f32x2 MSE.
// ---------------------------------------------------------------------------
#define ACCW(sw, nw, k, mp) do {                                              \
    __nv_bfloat162 _a = *reinterpret_cast<const __nv_bfloat162*>(&(nw));      \
    __nv_bfloat162 _b = *reinterpret_cast<const __nv_bfloat162*>(&(sw));      \
    __nv_bfloat162 _d = __hsub2(_a, _b);                                      \
    unsigned _du = *reinterpret_cast<unsigned*>(&_d);                         \
    float _lo = __uint_as_float(_du << 16);                                   \
    float _hi = __uint_as_float(_du & 0xffff0000u);                           \
    tv[(k)]     += fabsf(_lo);                                                \
    tv[(k) + 1] += fabsf(_hi);                                                \
    unsigned long long _dp;                                                   \
    asm("mov.b64 %0, {%1, %2};" : "=l"(_dp)                                   \
        : "r"(__float_as_uint(_lo)), "r"(__float_as_uint(_hi)));              \
    asm("fma.rn.f32x2 %0, %1, %2, %3;" : "=l"(mp)                             \
        : "l"(_dp), "l"(_dp), "l"(mp));                                       \
} while (0)

#define ACC4(s, nb) do {                                                      \
    ACCW((s).x, (nb).x, 0, msep[0]);                                          \
    ACCW((s).y, (nb).y, 2, msep[1]);                                          \
    ACCW((s).z, (nb).z, 4, msep[2]);                                          \
    ACCW((s).w, (nb).w, 6, msep[3]);                                          \
} while (0)

// ---------------------------------------------------------------------------
// Reduce (r5 proven tiling): grid = 16 y-octets x 32 z-quads, block = 8
// warps, warp = one y row, 4 z-plane loop. Records which interior self-chunks
// are nonzero; zeroes them after the block-wide sync (all reads complete).
// ---------------------------------------------------------------------------
__global__ void reduce_kernel() {
    const uint4* __restrict__ g4 = (const uint4*)g_grid;
    uint4* __restrict__ gw = (uint4*)g_grid;
    int tid  = threadIdx.x;
    int lane = tid & 31;
    int wrp  = tid >> 5;             // 0..7 ; y%8 == wrp
    int bg   = lane & 1;
    int xl   = lane >> 1;            // 0..15
    int y    = blockIdx.x * 8 + wrp; // 0..127
    bool yok = (y < XDIM - 1);
    bool inner_y = (wrp != 0);       // interior along y

    float tv[8];
    unsigned long long msep[4];
#pragma unroll
    for (int i = 0; i < 8; i++) tv[i] = 0.f;
#pragma unroll
    for (int i = 0; i < 4; i++) msep[i] = 0ull;

    unsigned zmask = 0u;             // bit zi*8+c: self chunk nonzero, interior

    for (int zi = 0; zi < 4; zi++) {
        int z = blockIdx.y * 4 + zi;
        bool zok = (z < XDIM - 1);
        bool inner = inner_y && (zi != 0);          // z%4 == zi
        size_t row2 = ((size_t)(z << 7) + y) * (XDIM * 2);  // uint4 idx at x=0

#pragma unroll
        for (int c = 0; c < 8; c++) {
            size_t i0 = row2 + c * 32 + lane;
            uint4 s = g4[i0];
            if (inner && ((s.x | s.y | s.z | s.w) != 0u))
                zmask |= (1u << (zi * 8 + c));

            if (c < 7) {
                uint4 nx = g4[i0 + 2];
                ACC4(s, nx);
            } else if (xl < 15) {                  // x = 112..126 only
                uint4 nx = g4[i0 + 2];
                ACC4(s, nx);
            }
            if (yok) { uint4 ny = g4[i0 + 2 * XDIM];        ACC4(s, ny); }
            if (zok) { uint4 nz = g4[i0 + 2 * XDIM * XDIM]; ACC4(s, nz); }
        }
    }

    // Unpack packed mse pairs.
    float mse[8];
#pragma unroll
    for (int i = 0; i < 4; i++) {
        unsigned _lo, _hi;
        asm("mov.b64 {%0, %1}, %2;" : "=r"(_lo), "=r"(_hi) : "l"(msep[i]));
        mse[2 * i]     = __uint_as_float(_lo);
        mse[2 * i + 1] = __uint_as_float(_hi);
    }

    // Warp reduce over lanes sharing bg (stride-2 lanes): xor 2,4,8,16.
#pragma unroll
    for (int off = 2; off <= 16; off <<= 1) {
#pragma unroll
        for (int i = 0; i < 8; i++) {
            tv[i]  += __shfl_xor_sync(0xffffffffu, tv[i],  off);
            mse[i] += __shfl_xor_sync(0xffffffffu, mse[i], off);
        }
    }

    __shared__ float s_tv[NB], s_mse[NB];
    if (tid < NB) { s_tv[tid] = 0.f; s_mse[tid] = 0.f; }
    __syncthreads();   // ALL grid reads by this block complete beyond here

    // Zero this block's touched interior chunks (exclusive ownership).
    if (zmask) {
        uint4 z4 = make_uint4(0u, 0u, 0u, 0u);
        for (int zi = 1; zi < 4; zi++) {
            if ((zmask >> (zi * 8)) & 0xffu) {
                int z = blockIdx.y * 4 + zi;
                size_t row2 = ((size_t)(z << 7) + y) * (XDIM * 2);
#pragma unroll
                for (int c = 0; c < 8; c++) {
                    if (zmask & (1u << (zi * 8 + c)))
                        gw[row2 + c * 32 + lane] = z4;
                }
            }
        }
    }

    if (lane < 2) {                  // lane 0 = bg0 totals, lane 1 = bg1
#pragma unroll
        for (int i = 0; i < 8; i++) {
            atomicAdd(&s_tv[bg * 8 + i],  tv[i]);
            atomicAdd(&s_mse[bg * 8 + i], mse[i]);
        }
    }
    __syncthreads();

    if (tid < NB) {
        atomicAdd(&g_acc[tid],      (double)s_tv[tid]);
        atomicAdd(&g_acc[NB + tid], (double)s_mse[tid]);
    }
}

// ---------------------------------------------------------------------------
// Zero only BOUNDARY touched voxels (y%8==0 || z%4==0 — the ones reduce
// blocks can't safely zero); last block finalizes.
// ---------------------------------------------------------------------------
__global__ void zero_fin_kernel(const int* __restrict__ idx, int N,
                                float* __restrict__ out) {
    if (blockIdx.x == gridDim.x - 1) {
        int t = threadIdx.x;
        if (t < 32) {
            double norm = (t < NB) ? (double)X3
                                   : (double)(2 * XDIM * XDIM - 2 * XDIM);
            out[t] = (float)(g_acc[t] / norm);
            g_acc[t] = 0.0;          // restore invariant for next replay
        }
        return;
    }
    int n = blockIdx.x * blockDim.x + threadIdx.x;
    if (n >= N) return;
    int z = __ldcs(idx + 3 * n + 0);
    int y = __ldcs(idx + 3 * n + 1);
    int x = __ldcs(idx + 3 * n + 2);
    if (((y & 7) == 0) || ((z & 3) == 0)) {
        ulonglong4* p =
            (ulonglong4*)(g_grid + (size_t)(((z << 7) + y) * XDIM + x) * NB);
        *p = make_ulonglong4(0ull, 0ull, 0ull, 0ull);
    }
}

extern "C" void kernel_launch(void* const* d_in, const int* in_sizes, int n_in,
                              void* d_out, int out_size) {
    const int*   indices = (const int*)d_in[0];
    const float* values  = (const float*)d_in[1];
    int N = in_sizes[0] / 3;        // 500000

    scatter_kernel<<<(N + 255) / 256, 256>>>(indices, values, N);
    reduce_kernel<<<dim3(16, 32), 256>>>();
    zero_fin_kernel<<<(N + 255) / 256 + 1, 256>>>(indices, N, (float*)d_out);
}

// round 14
// speedup vs baseline: 1.5713x; 1.0309x over previous
#include <cuda_runtime.h>
#include <cuda_bf16.h>
#include <cstdint>

#define XDIM 128
#define X3   (XDIM * XDIM * XDIM)   // 2,097,152 voxels
#define NB   16                     // batch

// Grid in bf16, batch-minor: g_grid[v*NB + b]. 64 MiB, zero-init at load.
// INVARIANT: all-zero at entry to every kernel_launch. Per launch:
// scatter -> reduce (self-zeroes nonzero INTERIOR voxels: y%8!=0 && z%4!=0,
// which only their own block reads) -> zero boundary voxels (y%8==0 ||
// z%4==0) + finalize. Nonzero bits <=> touched: bf16 accumulator starting at
// +0 under RN addition can never become -0.0 or a nonzero encoding of zero.
__device__ __nv_bfloat16 g_grid[(size_t)X3 * NB];
__device__ double g_acc[2 * NB];   // [0..15] tv sums, [16..31] mse sums

// ---------------------------------------------------------------------------
// Scatter (r5 proven): one thread per index; 2 x red.v4.bf16x2 (16 batches).
// ---------------------------------------------------------------------------
__global__ void scatter_kernel(const int* __restrict__ idx,
                               const float* __restrict__ vals, int N) {
    int n = blockIdx.x * blockDim.x + threadIdx.x;
    if (n >= N) return;
    int z = __ldcs(idx + 3 * n + 0);
    int y = __ldcs(idx + 3 * n + 1);
    int x = __ldcs(idx + 3 * n + 2);
    size_t v = (size_t)(((z << 7) + y) * XDIM + x);

    unsigned w[8];
#pragma unroll
    for (int g = 0; g < 8; g++) {
        float a = __ldcs(vals + (size_t)(2 * g) * N + n);
        float b = __ldcs(vals + (size_t)(2 * g + 1) * N + n);
        __nv_bfloat162 p = __floats2bfloat162_rn(a, b);
        w[g] = *reinterpret_cast<unsigned*>(&p);
    }

    __nv_bfloat16* base = g_grid + v * NB;
    asm volatile("red.global.add.noftz.v4.bf16x2 [%0], {%1, %2, %3, %4};"
                 :: "l"(base), "r"(w[0]), "r"(w[1]), "r"(w[2]), "r"(w[3])
                 : "memory");
    asm volatile("red.global.add.noftz.v4.bf16x2 [%0], {%1, %2, %3, %4};"
                 :: "l"(base + 8), "r"(w[4]), "r"(w[5]), "r"(w[6]), "r"(w[7])
                 : "memory");
}

// ---------------------------------------------------------------------------
// Packed diff-accumulate (proven r4): HADD2 diff, shl/and unpack, FADD |.|
// TV, packed fma.rn.f32x2 MSE.
// ---------------------------------------------------------------------------
#define ACCW(sw, nw, k, mp) do {                                              \
    __nv_bfloat162 _a = *reinterpret_cast<const __nv_bfloat162*>(&(nw));      \
    __nv_bfloat162 _b = *reinterpret_cast<const __nv_bfloat162*>(&(sw));      \
    __nv_bfloat162 _d = __hsub2(_a, _b);                                      \
    unsigned _du = *reinterpret_cast<unsigned*>(&_d);                         \
    float _lo = __uint_as_float(_du << 16);                                   \
    float _hi = __uint_as_float(_du & 0xffff0000u);                           \
    tv[(k)]     += fabsf(_lo);                                                \
    tv[(k) + 1] += fabsf(_hi);                                                \
    unsigned long long _dp;                                                   \
    asm("mov.b64 %0, {%1, %2};" : "=l"(_dp)                                   \
        : "r"(__float_as_uint(_lo)), "r"(__float_as_uint(_hi)));              \
    asm("fma.rn.f32x2 %0, %1, %2, %3;" : "=l"(mp)                             \
        : "l"(_dp), "l"(_dp), "l"(mp));                                       \
} while (0)

#define ACC4(s, nb) do {                                                      \
    ACCW((s).x, (nb).x, 0, msep[0]);                                          \
    ACCW((s).y, (nb).y, 2, msep[1]);                                          \
    ACCW((s).z, (nb).z, 4, msep[2]);                                          \
    ACCW((s).w, (nb).w, 6, msep[3]);                                          \
} while (0)

// ---------------------------------------------------------------------------
// Reduce (r5 proven tiling): grid = 16 y-octets x 32 z-quads, block = 8
// warps, warp = one y row, 4 z-plane loop. Records which interior self-chunks
// are nonzero; zeroes them after the block-wide sync (all reads complete).
// ---------------------------------------------------------------------------
__global__ void reduce_kernel() {
    const uint4* __restrict__ g4 = (const uint4*)g_grid;
    uint4* __restrict__ gw = (uint4*)g_grid;
    int tid  = threadIdx.x;
    int lane = tid & 31;
    int wrp  = tid >> 5;             // 0..7 ; y%8 == wrp
    int bg   = lane & 1;
    int xl   = lane >> 1;            // 0..15
    int y    = blockIdx.x * 8 + wrp; // 0..127
    bool yok = (y < XDIM - 1);
    bool inner_y = (wrp != 0);       // interior along y

    float tv[8];
    unsigned long long msep[4];
#pragma unroll
    for (int i = 0; i < 8; i++) tv[i] = 0.f;
#pragma unroll
    for (int i = 0; i < 4; i++) msep[i] = 0ull;

    unsigned zmask = 0u;             // bit zi*8+c: self chunk nonzero, interior

    for (int zi = 0; zi < 4; zi++) {
        int z = blockIdx.y * 4 + zi;
        bool zok = (z < XDIM - 1);
        bool inner = inner_y && (zi != 0);          // z%4 == zi
        size_t row2 = ((size_t)(z << 7) + y) * (XDIM * 2);  // uint4 idx at x=0

#pragma unroll
        for (int c = 0; c < 8; c++) {
            size_t i0 = row2 + c * 32 + lane;
            uint4 s = g4[i0];
            if (inner && ((s.x | s.y | s.z | s.w) != 0u))
                zmask |= (1u << (zi * 8 + c));

            if (c < 7) {
                uint4 nx = g4[i0 + 2];
                ACC4(s, nx);
            } else if (xl < 15) {                  // x = 112..126 only
                uint4 nx = g4[i0 + 2];
                ACC4(s, nx);
            }
            if (yok) { uint4 ny = g4[i0 + 2 * XDIM];        ACC4(s, ny); }
            if (zok) { uint4 nz = g4[i0 + 2 * XDIM * XDIM]; ACC4(s, nz); }
        }
    }

    // Unpack packed mse pairs.
    float mse[8];
#pragma unroll
    for (int i = 0; i < 4; i++) {
        unsigned _lo, _hi;
        asm("mov.b64 {%0, %1}, %2;" : "=r"(_lo), "=r"(_hi) : "l"(msep[i]));
        mse[2 * i]     = __uint_as_float(_lo);
        mse[2 * i + 1] = __uint_as_float(_hi);
    }

    // Warp reduce over lanes sharing bg (stride-2 lanes): xor 2,4,8,16.
#pragma unroll
    for (int off = 2; off <= 16; off <<= 1) {
#pragma unroll
        for (int i = 0; i < 8; i++) {
            tv[i]  += __shfl_xor_sync(0xffffffffu, tv[i],  off);
            mse[i] += __shfl_xor_sync(0xffffffffu, mse[i], off);
        }
    }

    __shared__ float s_tv[NB], s_mse[NB];
    if (tid < NB) { s_tv[tid] = 0.f; s_mse[tid] = 0.f; }
    __syncthreads();   // ALL grid reads by this block complete beyond here

    // Zero this block's touched interior chunks (exclusive ownership).
    if (zmask) {
        uint4 z4 = make_uint4(0u, 0u, 0u, 0u);
        for (int zi = 1; zi < 4; zi++) {
            if ((zmask >> (zi * 8)) & 0xffu) {
                int z = blockIdx.y * 4 + zi;
                size_t row2 = ((size_t)(z << 7) + y) * (XDIM * 2);
#pragma unroll
                for (int c = 0; c < 8; c++) {
                    if (zmask & (1u << (zi * 8 + c)))
                        gw[row2 + c * 32 + lane] = z4;
                }
            }
        }
    }

    if (lane < 2) {                  // lane 0 = bg0 totals, lane 1 = bg1
#pragma unroll
        for (int i = 0; i < 8; i++) {
            atomicAdd(&s_tv[bg * 8 + i],  tv[i]);
            atomicAdd(&s_mse[bg * 8 + i], mse[i]);
        }
    }
    __syncthreads();

    if (tid < NB) {
        atomicAdd(&g_acc[tid],      (double)s_tv[tid]);
        atomicAdd(&g_acc[NB + tid], (double)s_mse[tid]);
    }
}

// ---------------------------------------------------------------------------
// Zero only BOUNDARY touched voxels (y%8==0 || z%4==0 — the ones reduce
// blocks can't safely zero); last block finalizes.
// ---------------------------------------------------------------------------
__global__ void zero_fin_kernel(const int* __restrict__ idx, int N,
                                float* __restrict__ out) {
    if (blockIdx.x == gridDim.x - 1) {
        int t = threadIdx.x;
        if (t < 32) {
            double norm = (t < NB) ? (double)X3
                                   : (double)(2 * XDIM * XDIM - 2 * XDIM);
            out[t] = (float)(g_acc[t] / norm);
            g_acc[t] = 0.0;          // restore invariant for next replay
        }
        return;
    }
    int n = blockIdx.x * blockDim.x + threadIdx.x;
    if (n >= N) return;
    int z = __ldcs(idx + 3 * n + 0);
    int y = __ldcs(idx + 3 * n + 1);
    int x = __ldcs(idx + 3 * n + 2);
    if (((y & 7) == 0) || ((z & 3) == 0)) {
        ulonglong4* p =
            (ulonglong4*)(g_grid + (size_t)(((z << 7) + y) * XDIM + x) * NB);
        *p = make_ulonglong4(0ull, 0ull, 0ull, 0ull);
    }
}

extern "C" void kernel_launch(void* const* d_in, const int* in_sizes, int n_in,
                              void* d_out, int out_size) {
    const int*   indices = (const int*)d_in[0];
    const float* values  = (const float*)d_in[1];
    int N = in_sizes[0] / 3;        // 500000

    scatter_kernel<<<(N + 255) / 256, 256>>>(indices, values, N);
    reduce_kernel<<<dim3(16, 32), 256>>>();
    zero_fin_kernel<<<(N + 255) / 256 + 1, 256>>>(indices, N, (float*)d_out);
}